// round 16
// baseline (speedup 1.0000x reference)
#include <cuda_runtime.h>
#include <cuda_bf16.h>
#include <cuda_fp16.h>
#include <math.h>
#include <stdint.h>

#define M_TOTAL 131072  // 2048 windows * 64 tokens

// ---------------- scratch (device globals) ----------------
__device__ float         g_qkv[(size_t)M_TOTAL * 512];   // fp32 (qn|kn), pre-normalized
__device__ __half        g_v[(size_t)M_TOTAL * 256];     // v fp16-hi
__device__ __nv_bfloat16 g_a1[(size_t)M_TOTAL * 512];    // x split [hi|lo] (bf16)
__device__ __half        g_xh[(size_t)M_TOTAL * 256];    // x fp16-hi (for v GEMM)
__device__ __half        g_a2[(size_t)M_TOTAL * 256];    // attn-out fp16-hi
__device__ __nv_bfloat16 g_wq[768 * 768];                // qkv_w split [hi|hi|lo] (bf16)
__device__ __half        g_wv[256 * 256];                // qkv_w v-rows fp16-hi
__device__ __half        g_wp[256 * 256];                // proj_w hi (fp16)
__device__ float         g_bias16[8 * 64 * 64];          // 16*sigmoid(rpb), fragment-permuted cols
__device__ float         g_qkvbias[768];                 // [q_bias | 0 | v_bias]

// ---------------- PTX helpers (baseline ISA only) ----------------
__device__ __forceinline__ uint32_t smem_u32(const void* p) {
    uint32_t a;
    asm("{ .reg .u64 t; cvta.to.shared.u64 t, %1; cvt.u32.u64 %0, t; }" : "=r"(a) : "l"(p));
    return a;
}

#define CP_ASYNC16(dst, src) \
    asm volatile("cp.async.cg.shared.global [%0], [%1], 16;" :: "r"((uint32_t)(dst)), "l"(src))
#define CP_COMMIT() asm volatile("cp.async.commit_group;" ::: "memory")
#define CP_WAIT(n)  asm volatile("cp.async.wait_group %0;" :: "n"(n) : "memory")

#define LDSM_X4(r, addr) \
    asm volatile("ldmatrix.sync.aligned.m8n8.x4.shared.b16 {%0,%1,%2,%3}, [%4];" \
                 : "=r"((r)[0]), "=r"((r)[1]), "=r"((r)[2]), "=r"((r)[3]) : "r"(addr))

#define MMA16816(c, a, b0, b1) \
    asm volatile("mma.sync.aligned.m16n8k16.row.col.f32.bf16.bf16.f32 " \
                 "{%0,%1,%2,%3}, {%4,%5,%6,%7}, {%8,%9}, {%0,%1,%2,%3};" \
                 : "+f"((c)[0]), "+f"((c)[1]), "+f"((c)[2]), "+f"((c)[3]) \
                 : "r"((a)[0]), "r"((a)[1]), "r"((a)[2]), "r"((a)[3]), "r"(b0), "r"(b1))

#define MMA16816H(c, a, b0, b1) \
    asm volatile("mma.sync.aligned.m16n8k16.row.col.f32.f16.f16.f32 " \
                 "{%0,%1,%2,%3}, {%4,%5,%6,%7}, {%8,%9}, {%0,%1,%2,%3};" \
                 : "+f"((c)[0]), "+f"((c)[1]), "+f"((c)[2]), "+f"((c)[3]) \
                 : "r"((a)[0]), "r"((a)[1]), "r"((a)[2]), "r"((a)[3]), "r"(b0), "r"(b1))

__device__ __forceinline__ void split2(float v, unsigned short& h, unsigned short& l) {
    __nv_bfloat16 hb = __float2bfloat16_rn(v);
    float r = v - __bfloat162float(hb);
    __nv_bfloat16 lb = __float2bfloat16_rn(r);
    h = *(unsigned short*)&hb;
    l = *(unsigned short*)&lb;
}
__device__ __forceinline__ unsigned short h_of(float v) {
    __half hb = __float2half_rn(v);
    return *(unsigned short*)&hb;
}

// ---------------- fused prologue: prep (block 0) + split_act + split_wq + split_wp
#define ACT_BLOCKS 32768   // M_TOTAL*256 floats / (256 thr * 4)
#define WQ_BLOCKS 192      // 768*256 floats / (256 thr * 4)
#define WP_BLOCKS 64       // 256*256 floats / (256 thr * 4)
__global__ __launch_bounds__(256) void prep_all(
    const float* __restrict__ x, const float* __restrict__ qkv_w,
    const float* __restrict__ proj_w,
    const float* __restrict__ cpb_w1, const float* __restrict__ cpb_b1,
    const float* __restrict__ cpb_w2,
    const float* __restrict__ q_bias, const float* __restrict__ v_bias)
{
    const int bid = blockIdx.x;
    const int t = threadIdx.x;

    if (bid == 0) {
        __shared__ float bt[225][8];
        for (int i = t; i < 768; i += 256)
            g_qkvbias[i] = (i < 256) ? q_bias[i] : ((i < 512) ? 0.0f : v_bias[i - 512]);
        if (t < 225) {
            int i = t / 15, j = t % 15;
            float t0 = (float)(i - 7) * (8.0f / 7.0f);
            float t1 = (float)(j - 7) * (8.0f / 7.0f);
            t0 = copysignf(log2f(fabsf(t0) + 1.0f), t0) * (1.0f / 3.0f);
            t1 = copysignf(log2f(fabsf(t1) + 1.0f), t1) * (1.0f / 3.0f);
            float acc[8];
#pragma unroll
            for (int hh = 0; hh < 8; hh++) acc[hh] = 0.0f;
            for (int u = 0; u < 512; u++) {
                float hu = fmaxf(cpb_w1[2 * u] * t0 + cpb_w1[2 * u + 1] * t1 + cpb_b1[u], 0.0f);
#pragma unroll
                for (int hh = 0; hh < 8; hh++) acc[hh] += cpb_w2[hh * 512 + u] * hu;
            }
#pragma unroll
            for (int hh = 0; hh < 8; hh++) bt[t][hh] = acc[hh];
        }
        __syncthreads();
        for (int idx = t; idx < 8 * 64 * 64; idx += 256) {
            int hh = idx >> 12, n = (idx >> 6) & 63, m = idx & 63;
            int rid = ((n >> 3) - (m >> 3) + 7) * 15 + ((n & 7) - (m & 7) + 7);
            int newm = ((m >> 1) & 3) * 16 + (m >> 3) * 2 + (m & 1);
            g_bias16[((hh * 64 + n) << 6) + newm] = 16.0f / (1.0f + __expf(-bt[rid][hh]));
        }
        return;
    }

    if (bid <= ACT_BLOCKS) {
        size_t u = ((size_t)(bid - 1) * 256 + t) * 4;
        size_t row = u >> 8;
        int col = (int)(u & 255);
        float4 v = *(const float4*)(x + u);
        unsigned short h[4], l[4];
        split2(v.x, h[0], l[0]); split2(v.y, h[1], l[1]);
        split2(v.z, h[2], l[2]); split2(v.w, h[3], l[3]);
        uint2 hv, lv, fv;
        hv.x = (uint32_t)h[0] | ((uint32_t)h[1] << 16);
        hv.y = (uint32_t)h[2] | ((uint32_t)h[3] << 16);
        lv.x = (uint32_t)l[0] | ((uint32_t)l[1] << 16);
        lv.y = (uint32_t)l[2] | ((uint32_t)l[3] << 16);
        fv.x = (uint32_t)h_of(v.x) | ((uint32_t)h_of(v.y) << 16);
        fv.y = (uint32_t)h_of(v.z) | ((uint32_t)h_of(v.w) << 16);
        __nv_bfloat16* d = g_a1 + row * 512 + col;
        *(uint2*)d = hv;
        *(uint2*)(d + 256) = lv;
        *(uint2*)(g_xh + row * 256 + col) = fv;
        return;
    }

    if (bid <= ACT_BLOCKS + WQ_BLOCKS) {
        size_t u = ((size_t)(bid - 1 - ACT_BLOCKS) * 256 + t) * 4;
        size_t row = u >> 8;
        int col = (int)(u & 255);
        float4 v = *(const float4*)(qkv_w + u);
        unsigned short h[4], l[4];
        split2(v.x, h[0], l[0]); split2(v.y, h[1], l[1]);
        split2(v.z, h[2], l[2]); split2(v.w, h[3], l[3]);
        uint2 hv, lv;
        hv.x = (uint32_t)h[0] | ((uint32_t)h[1] << 16);
        hv.y = (uint32_t)h[2] | ((uint32_t)h[3] << 16);
        lv.x = (uint32_t)l[0] | ((uint32_t)l[1] << 16);
        lv.y = (uint32_t)l[2] | ((uint32_t)l[3] << 16);
        __nv_bfloat16* d = g_wq + row * 768 + col;
        *(uint2*)d = hv;
        *(uint2*)(d + 256) = hv;
        *(uint2*)(d + 512) = lv;
        if (row >= 512) {
            uint2 fv;
            fv.x = (uint32_t)h_of(v.x) | ((uint32_t)h_of(v.y) << 16);
            fv.y = (uint32_t)h_of(v.z) | ((uint32_t)h_of(v.w) << 16);
            *(uint2*)(g_wv + (row - 512) * 256 + col) = fv;
        }
        return;
    }

    {
        size_t u = ((size_t)(bid - 1 - ACT_BLOCKS - WQ_BLOCKS) * 256 + t) * 4;
        float4 v = *(const float4*)(proj_w + u);
        uint2 hv;
        hv.x = (uint32_t)h_of(v.x) | ((uint32_t)h_of(v.y) << 16);
        hv.y = (uint32_t)h_of(v.z) | ((uint32_t)h_of(v.w) << 16);
        *(uint2*)(g_wp + u) = hv;
    }
}

// ---------------- merged qk+v GEMM ----------------
__global__ __launch_bounds__(256, 2) void qkv_mma(const float* __restrict__ ls) {
    extern __shared__ __align__(128) char smem[];
    const uint32_t sbase = smem_u32(smem);
    const int t = threadIdx.x;
    const int lane = t & 31, wid = t >> 5;
    const size_t bm = (size_t)blockIdx.y * 128;
    const int wm = (wid >> 2) * 64;
    const int wn = (wid & 3) * 32;
    const int g = lane >> 2, tt = lane & 3;

    float acc[4][4][4];
#pragma unroll
    for (int mi = 0; mi < 4; mi++)
#pragma unroll
        for (int ni = 0; ni < 4; ni++)
#pragma unroll
            for (int q = 0; q < 4; q++) acc[mi][ni][q] = 0.0f;

    if (blockIdx.x < 4) {
        const int bn = blockIdx.x * 128;
        const char* Ag = (const char*)(g_a1 + bm * 512);
        const char* Wg = (const char*)(g_wq + (size_t)bn * 768);

        auto load_chunk = [&](int c, int s) {
            uint32_t ab = sbase + s * 32768;
            uint32_t bb = ab + 16384;
            const int sec = c >> 2;
            const int acol = (c & 3) * 64 + ((sec == 1) ? 256 : 0);
            const char* Ap = Ag + acol * 2;
            const char* Bp = Wg + c * 128;
#pragma unroll
            for (int i = 0; i < 4; i++) {
                int u = i * 256 + t;
                int row = u >> 3, c16 = u & 7;
                uint32_t off = (uint32_t)(row * 128 + ((c16 ^ (row & 7)) << 4));
                CP_ASYNC16(ab + off, Ap + (size_t)row * 1024 + c16 * 16);
                CP_ASYNC16(bb + off, Bp + (size_t)row * 1536 + c16 * 16);
            }
        };

        load_chunk(0, 0); CP_COMMIT();
        load_chunk(1, 1); CP_COMMIT();

        for (int c = 0; c < 12; c++) {
            if (c < 11) CP_WAIT(1); else CP_WAIT(0);
            __syncthreads();
            if (c + 2 < 12) { load_chunk(c + 2, (c + 2) % 3); CP_COMMIT(); }

            uint32_t ab = sbase + (c % 3) * 32768;
            uint32_t bb = ab + 16384;
#pragma unroll
            for (int ks = 0; ks < 4; ks++) {
                const int kc = ks * 2;
                uint32_t a_regs[4][4];
#pragma unroll
                for (int mi = 0; mi < 4; mi++) {
                    int r = wm + mi * 16 + (lane & 15);
                    int kk = kc + (lane >> 4);
                    LDSM_X4(a_regs[mi], ab + r * 128 + ((kk ^ (r & 7)) << 4));
                }
                uint32_t b_regs[2][4];
#pragma unroll
                for (int np = 0; np < 2; np++) {
                    int r = wn + np * 16 + (lane & 15);
                    int kk = kc + (lane >> 4);
                    LDSM_X4(b_regs[np], bb + r * 128 + ((kk ^ (r & 7)) << 4));
                }
#pragma unroll
                for (int mi = 0; mi < 4; mi++)
#pragma unroll
                    for (int ni = 0; ni < 4; ni++) {
                        uint32_t b0 = b_regs[ni >> 1][ni & 1];
                        uint32_t b1 = b_regs[ni >> 1][(ni & 1) + 2];
                        MMA16816(acc[mi][ni], a_regs[mi], b0, b1);
                    }
            }
        }

        const int cw = bn + wn;
        const bool isq = cw < 256;
        float scale = 1.0f;
        if (isq) scale = __expf(fminf(ls[cw >> 5], 4.6051702f));

#pragma unroll
        for (int mi = 0; mi < 4; mi++) {
            float ss0 = 0.0f, ss1 = 0.0f;
#pragma unroll
            for (int ni = 0; ni < 4; ni++) {
                int col = cw + ni * 8 + tt * 2;
                float b0 = g_qkvbias[col], b1 = g_qkvbias[col + 1];
                acc[mi][ni][0] += b0; acc[mi][ni][1] += b1;
                acc[mi][ni][2] += b0; acc[mi][ni][3] += b1;
                ss0 += acc[mi][ni][0] * acc[mi][ni][0] + acc[mi][ni][1] * acc[mi][ni][1];
                ss1 += acc[mi][ni][2] * acc[mi][ni][2] + acc[mi][ni][3] * acc[mi][ni][3];
            }
            size_t r0 = bm + wm + mi * 16 + g;
            ss0 += __shfl_xor_sync(0xffffffffu, ss0, 1);
            ss0 += __shfl_xor_sync(0xffffffffu, ss0, 2);
            ss1 += __shfl_xor_sync(0xffffffffu, ss1, 1);
            ss1 += __shfl_xor_sync(0xffffffffu, ss1, 2);
            float inv0 = scale / fmaxf(sqrtf(ss0), 1e-12f);
            float inv1 = scale / fmaxf(sqrtf(ss1), 1e-12f);
#pragma unroll
            for (int ni = 0; ni < 4; ni++) {
                int col = cw + ni * 8 + tt * 2;
                float2 v0 = make_float2(acc[mi][ni][0] * inv0, acc[mi][ni][1] * inv0);
                float2 v1 = make_float2(acc[mi][ni][2] * inv1, acc[mi][ni][3] * inv1);
                *(float2*)(g_qkv + r0 * 512 + col) = v0;
                *(float2*)(g_qkv + (r0 + 8) * 512 + col) = v1;
            }
        }
    } else {
        const int bn = (blockIdx.x - 4) * 128;
        const char* Ag = (const char*)g_xh + bm * 512;
        const char* Wg = (const char*)g_wv + (size_t)bn * 512;

        auto load_chunk = [&](int c, int s) {
            uint32_t ab = sbase + s * 32768;
            uint32_t bb = ab + 16384;
            const char* Ap = Ag + c * 128;
            const char* Bp = Wg + c * 128;
#pragma unroll
            for (int i = 0; i < 4; i++) {
                int u = i * 256 + t;
                int row = u >> 3, c16 = u & 7;
                uint32_t off = (uint32_t)(row * 128 + ((c16 ^ (row & 7)) << 4));
                CP_ASYNC16(ab + off, Ap + (size_t)row * 512 + c16 * 16);
                CP_ASYNC16(bb + off, Bp + (size_t)row * 512 + c16 * 16);
            }
        };

        load_chunk(0, 0); CP_COMMIT();
        load_chunk(1, 1); CP_COMMIT();

        for (int c = 0; c < 4; c++) {
            if (c < 3) CP_WAIT(1); else CP_WAIT(0);
            __syncthreads();
            if (c + 2 < 4) { load_chunk(c + 2, (c + 2) % 3); CP_COMMIT(); }

            uint32_t ab = sbase + (c % 3) * 32768;
            uint32_t bb = ab + 16384;
#pragma unroll
            for (int ks = 0; ks < 4; ks++) {
                const int kc = ks * 2;
                uint32_t a_regs[4][4];
#pragma unroll
                for (int mi = 0; mi < 4; mi++) {
                    int r = wm + mi * 16 + (lane & 15);
                    int kk = kc + (lane >> 4);
                    LDSM_X4(a_regs[mi], ab + r * 128 + ((kk ^ (r & 7)) << 4));
                }
                uint32_t b_regs[2][4];
#pragma unroll
                for (int np = 0; np < 2; np++) {
                    int r = wn + np * 16 + (lane & 15);
                    int kk = kc + (lane >> 4);
                    LDSM_X4(b_regs[np], bb + r * 128 + ((kk ^ (r & 7)) << 4));
                }
#pragma unroll
                for (int mi = 0; mi < 4; mi++)
#pragma unroll
                    for (int ni = 0; ni < 4; ni++) {
                        uint32_t b0 = b_regs[ni >> 1][ni & 1];
                        uint32_t b1 = b_regs[ni >> 1][(ni & 1) + 2];
                        MMA16816H(acc[mi][ni], a_regs[mi], b0, b1);
                    }
            }
        }

#pragma unroll
        for (int mi = 0; mi < 4; mi++) {
            size_t r0 = bm + wm + mi * 16 + g;
#pragma unroll
            for (int ni = 0; ni < 4; ni++) {
                int col = bn + wn + ni * 8 + tt * 2;
                float b0 = g_qkvbias[512 + col], b1 = g_qkvbias[513 + col];
                uint32_t p0 = (uint32_t)h_of(acc[mi][ni][0] + b0) | ((uint32_t)h_of(acc[mi][ni][1] + b1) << 16);
                uint32_t p1 = (uint32_t)h_of(acc[mi][ni][2] + b0) | ((uint32_t)h_of(acc[mi][ni][3] + b1) << 16);
                *(uint32_t*)(g_v + r0 * 256 + col) = p0;
                *(uint32_t*)(g_v + (r0 + 8) * 256 + col) = p1;
            }
        }
    }
}

// ---------------- proj GEMM: fp16 1-term (A=hi, W=hi), K'=256, 2 CTAs/SM --------
__global__ __launch_bounds__(256, 2) void proj_mma(const float* __restrict__ bias,
                                                   float* __restrict__ C) {
    extern __shared__ __align__(128) char smem[];
    const uint32_t sbase = smem_u32(smem);
    const int t = threadIdx.x;
    const int lane = t & 31, wid = t >> 5;
    const int bn = blockIdx.x * 128;
    const size_t bm = (size_t)blockIdx.y * 128;
    const int wm = (wid >> 2) * 64;
    const int wn = (wid & 3) * 32;

    const char* Ag = (const char*)g_a2 + bm * 512;
    const char* Wg = (const char*)g_wp + (size_t)bn * 512;

    auto load_chunk = [&](int c, int s) {
        uint32_t ab = sbase + s * 32768;
        uint32_t bb = ab + 16384;
        const char* Ap = Ag + c * 128;
        const char* Bp = Wg + c * 128;
#pragma unroll
        for (int i = 0; i < 4; i++) {
            int u = i * 256 + t;
            int row = u >> 3, c16 = u & 7;
            uint32_t off = (uint32_t)(row * 128 + ((c16 ^ (row & 7)) << 4));
            CP_ASYNC16(ab + off, Ap + (size_t)row * 512 + c16 * 16);
            CP_ASYNC16(bb + off, Bp + (size_t)row * 512 + c16 * 16);
        }
    };

    float acc[4][4][4];
#pragma unroll
    for (int mi = 0; mi < 4; mi++)
#pragma unroll
        for (int ni = 0; ni < 4; ni++)
#pragma unroll
            for (int q = 0; q < 4; q++) acc[mi][ni][q] = 0.0f;

    load_chunk(0, 0); CP_COMMIT();
    load_chunk(1, 1); CP_COMMIT();

    for (int c = 0; c < 4; c++) {
        if (c < 3) CP_WAIT(1); else CP_WAIT(0);
        __syncthreads();
        if (c + 2 < 4) { load_chunk(c + 2, (c + 2) % 3); CP_COMMIT(); }

        uint32_t ab = sbase + (c % 3) * 32768;
        uint32_t bb = ab + 16384;
#pragma unroll
        for (int ks = 0; ks < 4; ks++) {
            const int kc = ks * 2;
            uint32_t a_regs[4][4];
#pragma unroll
            for (int mi = 0; mi < 4; mi++) {
                int r = wm + mi * 16 + (lane & 15);
                int kk = kc + (lane >> 4);
                LDSM_X4(a_regs[mi], ab + r * 128 + ((kk ^ (r & 7)) << 4));
            }
            uint32_t b_regs[2][4];
#pragma unroll
            for (int np = 0; np < 2; np++) {
                int r = wn + np * 16 + (lane & 15);
                int kk = kc + (lane >> 4);
                LDSM_X4(b_regs[np], bb + r * 128 + ((kk ^ (r & 7)) << 4));
            }
#pragma unroll
            for (int mi = 0; mi < 4; mi++)
#pragma unroll
                for (int ni = 0; ni < 4; ni++) {
                    uint32_t b0 = b_regs[ni >> 1][ni & 1];
                    uint32_t b1 = b_regs[ni >> 1][(ni & 1) + 2];
                    MMA16816H(acc[mi][ni], a_regs[mi], b0, b1);
                }
        }
    }

    const int g = lane >> 2, tt = lane & 3;
#pragma unroll
    for (int mi = 0; mi < 4; mi++) {
        size_t r0 = bm + wm + mi * 16 + g;
#pragma unroll
        for (int ni = 0; ni < 4; ni++) {
            int col = bn + wn + ni * 8 + tt * 2;
            float bv0 = bias[col], bv1 = bias[col + 1];
            float2 v0 = make_float2(acc[mi][ni][0] + bv0, acc[mi][ni][1] + bv1);
            float2 v1 = make_float2(acc[mi][ni][2] + bv0, acc[mi][ni][3] + bv1);
            *(float2*)(C + r0 * 256 + col) = v0;
            *(float2*)(C + (r0 + 8) * 256 + col) = v1;
        }
    }
}

// ---------------- HMMA attention: 2 heads/block, 32 q-rows/warp (low-LDSM) -----
// per-head smem (31232B): Q'[h|l|h] 64x208 @0 ; K'[h|h|l] 64x208 @13312 ; VtH 32x144 @26624
// head hl region at smem + hl*31232. sO (fp32 64x36) reuses Q' region after sync.
#define ATTN_SMEM 62464
__global__ __launch_bounds__(128) void attn_mma() {
    extern __shared__ __align__(128) char smem[];
    const int b = blockIdx.x, hp = blockIdx.y;   // head pair
    const int t = threadIdx.x;
    const int lane = t & 31, w = t >> 5;
    const int hh = w >> 1;    // local head (0/1)
    const int wh = w & 1;     // warp within head
    const uint32_t sb = smem_u32(smem);

    // ---- q,k loader: both heads (8 iters x 128 thr = 2*64 rows * 8 d4-chunks) ----
#pragma unroll
    for (int i = 0; i < 8; i++) {
        int idx = t + i * 128;          // 0..1023
        int hl = idx >> 9;
        int n = (idx >> 3) & 63;
        int d4 = (idx & 7) << 2;
        const float* rb = g_qkv + (size_t)b * (64 * 512) + (hp * 2 + hl) * 32 + n * 512 + d4;
        float4 qv = *(const float4*)(rb);
        float4 kv = *(const float4*)(rb + 256);
        unsigned short qh[4], ql[4], kh[4], kl[4];
        split2(qv.x, qh[0], ql[0]); split2(qv.y, qh[1], ql[1]);
        split2(qv.z, qh[2], ql[2]); split2(qv.w, qh[3], ql[3]);
        split2(kv.x, kh[0], kl[0]); split2(kv.y, kh[1], kl[1]);
        split2(kv.z, kh[2], kl[2]); split2(kv.w, kh[3], kl[3]);
        uint2 qhv, qlv, khv, klv;
        qhv.x = (uint32_t)qh[0] | ((uint32_t)qh[1] << 16);
        qhv.y = (uint32_t)qh[2] | ((uint32_t)qh[3] << 16);
        qlv.x = (uint32_t)ql[0] | ((uint32_t)ql[1] << 16);
        qlv.y = (uint32_t)ql[2] | ((uint32_t)ql[3] << 16);
        khv.x = (uint32_t)kh[0] | ((uint32_t)kh[1] << 16);
        khv.y = (uint32_t)kh[2] | ((uint32_t)kh[3] << 16);
        klv.x = (uint32_t)kl[0] | ((uint32_t)kl[1] << 16);
        klv.y = (uint32_t)kl[2] | ((uint32_t)kl[3] << 16);
        char* qd = smem + hl * 31232 + n * 208 + d4 * 2;
        char* kd = smem + hl * 31232 + 13312 + n * 208 + d4 * 2;
        *(uint2*)(qd) = qhv; *(uint2*)(qd + 64) = qlv; *(uint2*)(qd + 128) = qhv;
        *(uint2*)(kd) = khv; *(uint2*)(kd + 64) = khv; *(uint2*)(kd + 128) = klv;
    }

    // ---- V loader: both heads ----
#pragma unroll
    for (int hl = 0; hl < 2; hl++) {
        int m = t >> 1, dh = (t & 1) * 16;
        const __half* vr = g_v + (size_t)(b * 64 + m) * 256 + (hp * 2 + hl) * 32 + dh;
        unsigned short vs[16];
        *(uint4*)(vs) = *(const uint4*)(vr);
        *(uint4*)(vs + 8) = *(const uint4*)(vr + 8);
        char* vth = smem + hl * 31232 + 26624;
#pragma unroll
        for (int i = 0; i < 16; i++)
            *(unsigned short*)(vth + (dh + i) * 144 + m * 2) = vs[i];
    }
    __syncthreads();

    // ---- QK^T: S(32x64) per warp (2 m16 tiles), K'=96 bf16 ----
    const int R = wh * 32;
    const uint32_t hb = sb + hh * 31232;
    const uint32_t qbase = hb;
    const uint32_t kbase = hb + 13312;
    float sacc[2][8][4];
#pragma unroll
    for (int mi = 0; mi < 2; mi++)
#pragma unroll
        for (int j = 0; j < 8; j++)
#pragma unroll
            for (int q = 0; q < 4; q++) sacc[mi][j][q] = 0.0f;

#pragma unroll
    for (int kk = 0; kk < 6; kk++) {
        const int ch = 2 * kk + (lane >> 4);
        uint32_t a[2][4];
#pragma unroll
        for (int mi = 0; mi < 2; mi++) {
            int r = R + mi * 16 + (lane & 15);
            LDSM_X4(a[mi], qbase + r * 208 + ch * 16);
        }
#pragma unroll
        for (int nt = 0; nt < 4; nt++) {
            uint32_t br[4];
            int r = nt * 16 + (lane & 15);
            LDSM_X4(br, kbase + r * 208 + ch * 16);
#pragma unroll
            for (int mi = 0; mi < 2; mi++) {
                MMA16816(sacc[mi][nt * 2 + 0], a[mi], br[0], br[2]);
                MMA16816(sacc[mi][nt * 2 + 1], a[mi], br[1], br[3]);
            }
        }
    }

    // ---- bias (fragment-permuted float4) + softmax, per mi ----
    const int g = lane >> 2, tt = lane & 3;
    const int h = hp * 2 + hh;
    float rc0[2], rc1[2];
#pragma unroll
    for (int mi = 0; mi < 2; mi++) {
        const float* bp0 = g_bias16 + (((h * 64 + R + mi * 16 + g) << 6) + tt * 16);
        const float* bp1 = bp0 + (8 << 6);
#pragma unroll
        for (int q = 0; q < 4; q++) {
            float4 c0 = *(const float4*)(bp0 + q * 4);
            float4 c1 = *(const float4*)(bp1 + q * 4);
            sacc[mi][2 * q + 0][0] += c0.x; sacc[mi][2 * q + 0][1] += c0.y;
            sacc[mi][2 * q + 1][0] += c0.z; sacc[mi][2 * q + 1][1] += c0.w;
            sacc[mi][2 * q + 0][2] += c1.x; sacc[mi][2 * q + 0][3] += c1.y;
            sacc[mi][2 * q + 1][2] += c1.z; sacc[mi][2 * q + 1][3] += c1.w;
        }
        float m0 = -1e30f, m1 = -1e30f;
#pragma unroll
        for (int j = 0; j < 8; j++) {
            m0 = fmaxf(m0, fmaxf(sacc[mi][j][0], sacc[mi][j][1]));
            m1 = fmaxf(m1, fmaxf(sacc[mi][j][2], sacc[mi][j][3]));
        }
        m0 = fmaxf(m0, __shfl_xor_sync(0xffffffffu, m0, 1));
        m0 = fmaxf(m0, __shfl_xor_sync(0xffffffffu, m0, 2));
        m1 = fmaxf(m1, __shfl_xor_sync(0xffffffffu, m1, 1));
        m1 = fmaxf(m1, __shfl_xor_sync(0xffffffffu, m1, 2));
        float s0 = 0.0f, s1 = 0.0f;
#pragma unroll
        for (int j = 0; j < 8; j++) {
            sacc[mi][j][0] = __expf(sacc[mi][j][0] - m0);
            sacc[mi][j][1] = __expf(sacc[mi][j][1] - m0);
            sacc[mi][j][2] = __expf(sacc[mi][j][2] - m1);
            sacc[mi][j][3] = __expf(sacc[mi][j][3] - m1);
            s0 += sacc[mi][j][0] + sacc[mi][j][1];
            s1 += sacc[mi][j][2] + sacc[mi][j][3];
        }
        s0 += __shfl_xor_sync(0xffffffffu, s0, 1);
        s0 += __shfl_xor_sync(0xffffffffu, s0, 2);
        s1 += __shfl_xor_sync(0xffffffffu, s1, 1);
        s1 += __shfl_xor_sync(0xffffffffu, s1, 2);
        rc0[mi] = 1.0f / s0;
        rc1[mi] = 1.0f / s1;
    }

    // ---- P fp16-hi B-fragments ----
    uint32_t bh[2][8][2];
#pragma unroll
    for (int mi = 0; mi < 2; mi++)
#pragma unroll
        for (int j = 0; j < 8; j++) {
            float p0 = sacc[mi][j][0] * rc0[mi], p1 = sacc[mi][j][1] * rc0[mi];
            float p2 = sacc[mi][j][2] * rc1[mi], p3 = sacc[mi][j][3] * rc1[mi];
            bh[mi][j][0] = (uint32_t)h_of(p0) | ((uint32_t)h_of(p1) << 16);
            bh[mi][j][1] = (uint32_t)h_of(p2) | ((uint32_t)h_of(p3) << 16);
        }

    // ---- O^T = V^T P^T: single fp16 pass, N=32 q-rows ----
    float oacc[2][2][2][4];  // [mt][mi][pair]
#pragma unroll
    for (int mt = 0; mt < 2; mt++)
#pragma unroll
        for (int mi = 0; mi < 2; mi++)
#pragma unroll
            for (int p = 0; p < 2; p++)
#pragma unroll
                for (int q = 0; q < 4; q++) oacc[mt][mi][p][q] = 0.0f;

    {
        const uint32_t vbase = hb + 26624;
#pragma unroll
        for (int mt = 0; mt < 2; mt++) {
#pragma unroll
            for (int s = 0; s < 4; s++) {
                uint32_t a[4];
                int r = mt * 16 + (lane & 15);
                int ch = 2 * s + (lane >> 4);
                LDSM_X4(a, vbase + r * 144 + ch * 16);
#pragma unroll
                for (int mi = 0; mi < 2; mi++) {
                    MMA16816H(oacc[mt][mi][0], a, bh[mi][2 * s][0], bh[mi][2 * s + 1][0]);
                    MMA16816H(oacc[mt][mi][1], a, bh[mi][2 * s][1], bh[mi][2 * s + 1][1]);
                }
            }
        }
    }

    // ---- stage O (transpose back) per head region, coalesced fp16-hi write ----
    __syncthreads();
    float* sO = (float*)(smem + hh * 31232);  // 64x36 fp32 per head
#pragma unroll
    for (int mt = 0; mt < 2; mt++)
#pragma unroll
        for (int mi = 0; mi < 2; mi++)
#pragma unroll
            for (int p = 0; p < 2; p++) {
                int qr = R + mi * 16 + p * 8 + tt * 2;
                int d = mt * 16 + g;
                sO[qr * 36 + d] = oacc[mt][mi][p][0];
                sO[(qr + 1) * 36 + d] = oacc[mt][mi][p][1];
                sO[qr * 36 + d + 8] = oacc[mt][mi][p][2];
                sO[(qr + 1) * 36 + d + 8] = oacc[mt][mi][p][3];
            }
    __syncthreads();

#pragma unroll
    for (int hl = 0; hl < 2; hl++) {
        int qr = t >> 1, dh = (t & 1) * 16;
        const float* orow = (const float*)(smem + hl * 31232) + qr * 36 + dh;
        unsigned short hi[16];
#pragma unroll
        for (int i = 0; i < 16; i++) hi[i] = h_of(orow[i]);
        __half* og = g_a2 + (size_t)(b * 64 + qr) * 256 + (hp * 2 + hl) * 32 + dh;
        uint4 hv0, hv1;
        hv0.x = (uint32_t)hi[0] | ((uint32_t)hi[1] << 16);
        hv0.y = (uint32_t)hi[2] | ((uint32_t)hi[3] << 16);
        hv0.z = (uint32_t)hi[4] | ((uint32_t)hi[5] << 16);
        hv0.w = (uint32_t)hi[6] | ((uint32_t)hi[7] << 16);
        hv1.x = (uint32_t)hi[8] | ((uint32_t)hi[9] << 16);
        hv1.y = (uint32_t)hi[10] | ((uint32_t)hi[11] << 16);
        hv1.z = (uint32_t)hi[12] | ((uint32_t)hi[13] << 16);
        hv1.w = (uint32_t)hi[14] | ((uint32_t)hi[15] << 16);
        *(uint4*)(og) = hv0;
        *(uint4*)(og + 8) = hv1;
    }
}

extern "C" void kernel_launch(void* const* d_in, const int* in_sizes, int n_in,
                              void* d_out, int out_size) {
    const float* x           = (const float*)d_in[0];
    const float* qkv_w       = (const float*)d_in[1];
    const float* q_bias      = (const float*)d_in[2];
    const float* v_bias      = (const float*)d_in[3];
    const float* logit_scale = (const float*)d_in[4];
    const float* cpb_w1      = (const float*)d_in[5];
    const float* cpb_b1      = (const float*)d_in[6];
    const float* cpb_w2      = (const float*)d_in[7];
    const float* proj_w      = (const float*)d_in[8];
    const float* proj_b      = (const float*)d_in[9];
    float* out = (float*)d_out;

    const int GEMM_SMEM = 3 * 32768;  // 96 KB, 2 CTAs/SM
    cudaFuncSetAttribute(qkv_mma, cudaFuncAttributeMaxDynamicSharedMemorySize, GEMM_SMEM);
    cudaFuncSetAttribute(proj_mma, cudaFuncAttributeMaxDynamicSharedMemorySize, GEMM_SMEM);
    cudaFuncSetAttribute(attn_mma, cudaFuncAttributeMaxDynamicSharedMemorySize, ATTN_SMEM);

    prep_all<<<1 + ACT_BLOCKS + WQ_BLOCKS + WP_BLOCKS, 256>>>(
        x, qkv_w, proj_w, cpb_w1, cpb_b1, cpb_w2, q_bias, v_bias);
    qkv_mma<<<dim3(6, M_TOTAL / 128), 256, GEMM_SMEM>>>(logit_scale);
    attn_mma<<<dim3(2048, 4), 128, ATTN_SMEM>>>();
    proj_mma<<<dim3(2, M_TOTAL / 128), 256, GEMM_SMEM>>>(proj_b, out);
}

// round 17
// speedup vs baseline: 1.0622x; 1.0622x over previous
#include <cuda_runtime.h>
#include <cuda_bf16.h>
#include <cuda_fp16.h>
#include <math.h>
#include <stdint.h>

#define M_TOTAL 131072  // 2048 windows * 64 tokens

// ---------------- scratch (device globals) ----------------
__device__ float         g_qkv[(size_t)M_TOTAL * 512];   // fp32 (qn|kn), pre-normalized
__device__ __half        g_v[(size_t)M_TOTAL * 256];     // v fp16-hi
__device__ __nv_bfloat16 g_a1[(size_t)M_TOTAL * 512];    // x split [hi|lo] (bf16)
__device__ __half        g_xh[(size_t)M_TOTAL * 256];    // x fp16-hi (for v GEMM)
__device__ __half        g_a2[(size_t)M_TOTAL * 256];    // attn-out fp16-hi
__device__ __nv_bfloat16 g_wq[768 * 768];                // qkv_w split [hi|hi|lo] (bf16)
__device__ __half        g_wv[256 * 256];                // qkv_w v-rows fp16-hi
__device__ __half        g_wp[256 * 256];                // proj_w hi (fp16)
__device__ float         g_bias16[8 * 64 * 64];          // 16*sigmoid(rpb), fragment-permuted cols
__device__ float         g_qkvbias[768];                 // [q_bias | 0 | v_bias]

// ---------------- PTX helpers (baseline ISA only) ----------------
__device__ __forceinline__ uint32_t smem_u32(const void* p) {
    uint32_t a;
    asm("{ .reg .u64 t; cvta.to.shared.u64 t, %1; cvt.u32.u64 %0, t; }" : "=r"(a) : "l"(p));
    return a;
}

#define CP_ASYNC16(dst, src) \
    asm volatile("cp.async.cg.shared.global [%0], [%1], 16;" :: "r"((uint32_t)(dst)), "l"(src))
#define CP_COMMIT() asm volatile("cp.async.commit_group;" ::: "memory")
#define CP_WAIT(n)  asm volatile("cp.async.wait_group %0;" :: "n"(n) : "memory")

#define LDSM_X4(r, addr) \
    asm volatile("ldmatrix.sync.aligned.m8n8.x4.shared.b16 {%0,%1,%2,%3}, [%4];" \
                 : "=r"((r)[0]), "=r"((r)[1]), "=r"((r)[2]), "=r"((r)[3]) : "r"(addr))

#define MMA16816(c, a, b0, b1) \
    asm volatile("mma.sync.aligned.m16n8k16.row.col.f32.bf16.bf16.f32 " \
                 "{%0,%1,%2,%3}, {%4,%5,%6,%7}, {%8,%9}, {%0,%1,%2,%3};" \
                 : "+f"((c)[0]), "+f"((c)[1]), "+f"((c)[2]), "+f"((c)[3]) \
                 : "r"((a)[0]), "r"((a)[1]), "r"((a)[2]), "r"((a)[3]), "r"(b0), "r"(b1))

#define MMA16816H(c, a, b0, b1) \
    asm volatile("mma.sync.aligned.m16n8k16.row.col.f32.f16.f16.f32 " \
                 "{%0,%1,%2,%3}, {%4,%5,%6,%7}, {%8,%9}, {%0,%1,%2,%3};" \
                 : "+f"((c)[0]), "+f"((c)[1]), "+f"((c)[2]), "+f"((c)[3]) \
                 : "r"((a)[0]), "r"((a)[1]), "r"((a)[2]), "r"((a)[3]), "r"(b0), "r"(b1))

__device__ __forceinline__ void split2(float v, unsigned short& h, unsigned short& l) {
    __nv_bfloat16 hb = __float2bfloat16_rn(v);
    float r = v - __bfloat162float(hb);
    __nv_bfloat16 lb = __float2bfloat16_rn(r);
    h = *(unsigned short*)&hb;
    l = *(unsigned short*)&lb;
}
__device__ __forceinline__ unsigned short h_of(float v) {
    __half hb = __float2half_rn(v);
    return *(unsigned short*)&hb;
}

// ---------------- fused prologue: prep (block 0) + split_act + split_wq + split_wp
#define ACT_BLOCKS 32768   // M_TOTAL*256 floats / (256 thr * 4)
#define WQ_BLOCKS 192      // 768*256 floats / (256 thr * 4)
#define WP_BLOCKS 64       // 256*256 floats / (256 thr * 4)
__global__ __launch_bounds__(256) void prep_all(
    const float* __restrict__ x, const float* __restrict__ qkv_w,
    const float* __restrict__ proj_w,
    const float* __restrict__ cpb_w1, const float* __restrict__ cpb_b1,
    const float* __restrict__ cpb_w2,
    const float* __restrict__ q_bias, const float* __restrict__ v_bias)
{
    const int bid = blockIdx.x;
    const int t = threadIdx.x;

    if (bid == 0) {
        __shared__ float bt[225][8];
        for (int i = t; i < 768; i += 256)
            g_qkvbias[i] = (i < 256) ? q_bias[i] : ((i < 512) ? 0.0f : v_bias[i - 512]);
        if (t < 225) {
            int i = t / 15, j = t % 15;
            float t0 = (float)(i - 7) * (8.0f / 7.0f);
            float t1 = (float)(j - 7) * (8.0f / 7.0f);
            t0 = copysignf(log2f(fabsf(t0) + 1.0f), t0) * (1.0f / 3.0f);
            t1 = copysignf(log2f(fabsf(t1) + 1.0f), t1) * (1.0f / 3.0f);
            float acc[8];
#pragma unroll
            for (int hh = 0; hh < 8; hh++) acc[hh] = 0.0f;
            for (int u = 0; u < 512; u++) {
                float hu = fmaxf(cpb_w1[2 * u] * t0 + cpb_w1[2 * u + 1] * t1 + cpb_b1[u], 0.0f);
#pragma unroll
                for (int hh = 0; hh < 8; hh++) acc[hh] += cpb_w2[hh * 512 + u] * hu;
            }
#pragma unroll
            for (int hh = 0; hh < 8; hh++) bt[t][hh] = acc[hh];
        }
        __syncthreads();
        for (int idx = t; idx < 8 * 64 * 64; idx += 256) {
            int hh = idx >> 12, n = (idx >> 6) & 63, m = idx & 63;
            int rid = ((n >> 3) - (m >> 3) + 7) * 15 + ((n & 7) - (m & 7) + 7);
            int newm = ((m >> 1) & 3) * 16 + (m >> 3) * 2 + (m & 1);
            g_bias16[((hh * 64 + n) << 6) + newm] = 16.0f / (1.0f + __expf(-bt[rid][hh]));
        }
        return;
    }

    if (bid <= ACT_BLOCKS) {
        size_t u = ((size_t)(bid - 1) * 256 + t) * 4;
        size_t row = u >> 8;
        int col = (int)(u & 255);
        float4 v = *(const float4*)(x + u);
        unsigned short h[4], l[4];
        split2(v.x, h[0], l[0]); split2(v.y, h[1], l[1]);
        split2(v.z, h[2], l[2]); split2(v.w, h[3], l[3]);
        uint2 hv, lv, fv;
        hv.x = (uint32_t)h[0] | ((uint32_t)h[1] << 16);
        hv.y = (uint32_t)h[2] | ((uint32_t)h[3] << 16);
        lv.x = (uint32_t)l[0] | ((uint32_t)l[1] << 16);
        lv.y = (uint32_t)l[2] | ((uint32_t)l[3] << 16);
        fv.x = (uint32_t)h_of(v.x) | ((uint32_t)h_of(v.y) << 16);
        fv.y = (uint32_t)h_of(v.z) | ((uint32_t)h_of(v.w) << 16);
        __nv_bfloat16* d = g_a1 + row * 512 + col;
        *(uint2*)d = hv;
        *(uint2*)(d + 256) = lv;
        *(uint2*)(g_xh + row * 256 + col) = fv;
        return;
    }

    if (bid <= ACT_BLOCKS + WQ_BLOCKS) {
        size_t u = ((size_t)(bid - 1 - ACT_BLOCKS) * 256 + t) * 4;
        size_t row = u >> 8;
        int col = (int)(u & 255);
        float4 v = *(const float4*)(qkv_w + u);
        unsigned short h[4], l[4];
        split2(v.x, h[0], l[0]); split2(v.y, h[1], l[1]);
        split2(v.z, h[2], l[2]); split2(v.w, h[3], l[3]);
        uint2 hv, lv;
        hv.x = (uint32_t)h[0] | ((uint32_t)h[1] << 16);
        hv.y = (uint32_t)h[2] | ((uint32_t)h[3] << 16);
        lv.x = (uint32_t)l[0] | ((uint32_t)l[1] << 16);
        lv.y = (uint32_t)l[2] | ((uint32_t)l[3] << 16);
        __nv_bfloat16* d = g_wq + row * 768 + col;
        *(uint2*)d = hv;
        *(uint2*)(d + 256) = hv;
        *(uint2*)(d + 512) = lv;
        if (row >= 512) {
            uint2 fv;
            fv.x = (uint32_t)h_of(v.x) | ((uint32_t)h_of(v.y) << 16);
            fv.y = (uint32_t)h_of(v.z) | ((uint32_t)h_of(v.w) << 16);
            *(uint2*)(g_wv + (row - 512) * 256 + col) = fv;
        }
        return;
    }

    {
        size_t u = ((size_t)(bid - 1 - ACT_BLOCKS - WQ_BLOCKS) * 256 + t) * 4;
        float4 v = *(const float4*)(proj_w + u);
        uint2 hv;
        hv.x = (uint32_t)h_of(v.x) | ((uint32_t)h_of(v.y) << 16);
        hv.y = (uint32_t)h_of(v.z) | ((uint32_t)h_of(v.w) << 16);
        *(uint2*)(g_wp + u) = hv;
    }
}

// ---------------- merged qk+v GEMM (R15) ----------------
__global__ __launch_bounds__(256, 2) void qkv_mma(const float* __restrict__ ls) {
    extern __shared__ __align__(128) char smem[];
    const uint32_t sbase = smem_u32(smem);
    const int t = threadIdx.x;
    const int lane = t & 31, wid = t >> 5;
    const size_t bm = (size_t)blockIdx.y * 128;
    const int wm = (wid >> 2) * 64;
    const int wn = (wid & 3) * 32;
    const int g = lane >> 2, tt = lane & 3;

    float acc[4][4][4];
#pragma unroll
    for (int mi = 0; mi < 4; mi++)
#pragma unroll
        for (int ni = 0; ni < 4; ni++)
#pragma unroll
            for (int q = 0; q < 4; q++) acc[mi][ni][q] = 0.0f;

    if (blockIdx.x < 4) {
        const int bn = blockIdx.x * 128;
        const char* Ag = (const char*)(g_a1 + bm * 512);
        const char* Wg = (const char*)(g_wq + (size_t)bn * 768);

        auto load_chunk = [&](int c, int s) {
            uint32_t ab = sbase + s * 32768;
            uint32_t bb = ab + 16384;
            const int sec = c >> 2;
            const int acol = (c & 3) * 64 + ((sec == 1) ? 256 : 0);
            const char* Ap = Ag + acol * 2;
            const char* Bp = Wg + c * 128;
#pragma unroll
            for (int i = 0; i < 4; i++) {
                int u = i * 256 + t;
                int row = u >> 3, c16 = u & 7;
                uint32_t off = (uint32_t)(row * 128 + ((c16 ^ (row & 7)) << 4));
                CP_ASYNC16(ab + off, Ap + (size_t)row * 1024 + c16 * 16);
                CP_ASYNC16(bb + off, Bp + (size_t)row * 1536 + c16 * 16);
            }
        };

        load_chunk(0, 0); CP_COMMIT();
        load_chunk(1, 1); CP_COMMIT();

        for (int c = 0; c < 12; c++) {
            if (c < 11) CP_WAIT(1); else CP_WAIT(0);
            __syncthreads();
            if (c + 2 < 12) { load_chunk(c + 2, (c + 2) % 3); CP_COMMIT(); }

            uint32_t ab = sbase + (c % 3) * 32768;
            uint32_t bb = ab + 16384;
#pragma unroll
            for (int ks = 0; ks < 4; ks++) {
                const int kc = ks * 2;
                uint32_t a_regs[4][4];
#pragma unroll
                for (int mi = 0; mi < 4; mi++) {
                    int r = wm + mi * 16 + (lane & 15);
                    int kk = kc + (lane >> 4);
                    LDSM_X4(a_regs[mi], ab + r * 128 + ((kk ^ (r & 7)) << 4));
                }
                uint32_t b_regs[2][4];
#pragma unroll
                for (int np = 0; np < 2; np++) {
                    int r = wn + np * 16 + (lane & 15);
                    int kk = kc + (lane >> 4);
                    LDSM_X4(b_regs[np], bb + r * 128 + ((kk ^ (r & 7)) << 4));
                }
#pragma unroll
                for (int mi = 0; mi < 4; mi++)
#pragma unroll
                    for (int ni = 0; ni < 4; ni++) {
                        uint32_t b0 = b_regs[ni >> 1][ni & 1];
                        uint32_t b1 = b_regs[ni >> 1][(ni & 1) + 2];
                        MMA16816(acc[mi][ni], a_regs[mi], b0, b1);
                    }
            }
        }

        const int cw = bn + wn;
        const bool isq = cw < 256;
        float scale = 1.0f;
        if (isq) scale = __expf(fminf(ls[cw >> 5], 4.6051702f));

#pragma unroll
        for (int mi = 0; mi < 4; mi++) {
            float ss0 = 0.0f, ss1 = 0.0f;
#pragma unroll
            for (int ni = 0; ni < 4; ni++) {
                int col = cw + ni * 8 + tt * 2;
                float b0 = g_qkvbias[col], b1 = g_qkvbias[col + 1];
                acc[mi][ni][0] += b0; acc[mi][ni][1] += b1;
                acc[mi][ni][2] += b0; acc[mi][ni][3] += b1;
                ss0 += acc[mi][ni][0] * acc[mi][ni][0] + acc[mi][ni][1] * acc[mi][ni][1];
                ss1 += acc[mi][ni][2] * acc[mi][ni][2] + acc[mi][ni][3] * acc[mi][ni][3];
            }
            size_t r0 = bm + wm + mi * 16 + g;
            ss0 += __shfl_xor_sync(0xffffffffu, ss0, 1);
            ss0 += __shfl_xor_sync(0xffffffffu, ss0, 2);
            ss1 += __shfl_xor_sync(0xffffffffu, ss1, 1);
            ss1 += __shfl_xor_sync(0xffffffffu, ss1, 2);
            float inv0 = scale / fmaxf(sqrtf(ss0), 1e-12f);
            float inv1 = scale / fmaxf(sqrtf(ss1), 1e-12f);
#pragma unroll
            for (int ni = 0; ni < 4; ni++) {
                int col = cw + ni * 8 + tt * 2;
                float2 v0 = make_float2(acc[mi][ni][0] * inv0, acc[mi][ni][1] * inv0);
                float2 v1 = make_float2(acc[mi][ni][2] * inv1, acc[mi][ni][3] * inv1);
                *(float2*)(g_qkv + r0 * 512 + col) = v0;
                *(float2*)(g_qkv + (r0 + 8) * 512 + col) = v1;
            }
        }
    } else {
        const int bn = (blockIdx.x - 4) * 128;
        const char* Ag = (const char*)g_xh + bm * 512;
        const char* Wg = (const char*)g_wv + (size_t)bn * 512;

        auto load_chunk = [&](int c, int s) {
            uint32_t ab = sbase + s * 32768;
            uint32_t bb = ab + 16384;
            const char* Ap = Ag + c * 128;
            const char* Bp = Wg + c * 128;
#pragma unroll
            for (int i = 0; i < 4; i++) {
                int u = i * 256 + t;
                int row = u >> 3, c16 = u & 7;
                uint32_t off = (uint32_t)(row * 128 + ((c16 ^ (row & 7)) << 4));
                CP_ASYNC16(ab + off, Ap + (size_t)row * 512 + c16 * 16);
                CP_ASYNC16(bb + off, Bp + (size_t)row * 512 + c16 * 16);
            }
        };

        load_chunk(0, 0); CP_COMMIT();
        load_chunk(1, 1); CP_COMMIT();

        for (int c = 0; c < 4; c++) {
            if (c < 3) CP_WAIT(1); else CP_WAIT(0);
            __syncthreads();
            if (c + 2 < 4) { load_chunk(c + 2, (c + 2) % 3); CP_COMMIT(); }

            uint32_t ab = sbase + (c % 3) * 32768;
            uint32_t bb = ab + 16384;
#pragma unroll
            for (int ks = 0; ks < 4; ks++) {
                const int kc = ks * 2;
                uint32_t a_regs[4][4];
#pragma unroll
                for (int mi = 0; mi < 4; mi++) {
                    int r = wm + mi * 16 + (lane & 15);
                    int kk = kc + (lane >> 4);
                    LDSM_X4(a_regs[mi], ab + r * 128 + ((kk ^ (r & 7)) << 4));
                }
                uint32_t b_regs[2][4];
#pragma unroll
                for (int np = 0; np < 2; np++) {
                    int r = wn + np * 16 + (lane & 15);
                    int kk = kc + (lane >> 4);
                    LDSM_X4(b_regs[np], bb + r * 128 + ((kk ^ (r & 7)) << 4));
                }
#pragma unroll
                for (int mi = 0; mi < 4; mi++)
#pragma unroll
                    for (int ni = 0; ni < 4; ni++) {
                        uint32_t b0 = b_regs[ni >> 1][ni & 1];
                        uint32_t b1 = b_regs[ni >> 1][(ni & 1) + 2];
                        MMA16816H(acc[mi][ni], a_regs[mi], b0, b1);
                    }
            }
        }

#pragma unroll
        for (int mi = 0; mi < 4; mi++) {
            size_t r0 = bm + wm + mi * 16 + g;
#pragma unroll
            for (int ni = 0; ni < 4; ni++) {
                int col = bn + wn + ni * 8 + tt * 2;
                float b0 = g_qkvbias[512 + col], b1 = g_qkvbias[513 + col];
                uint32_t p0 = (uint32_t)h_of(acc[mi][ni][0] + b0) | ((uint32_t)h_of(acc[mi][ni][1] + b1) << 16);
                uint32_t p1 = (uint32_t)h_of(acc[mi][ni][2] + b0) | ((uint32_t)h_of(acc[mi][ni][3] + b1) << 16);
                *(uint32_t*)(g_v + r0 * 256 + col) = p0;
                *(uint32_t*)(g_v + (r0 + 8) * 256 + col) = p1;
            }
        }
    }
}

// ---------------- proj GEMM: fp16 1-term (A=hi, W=hi), K'=256, 2 CTAs/SM --------
__global__ __launch_bounds__(256, 2) void proj_mma(const float* __restrict__ bias,
                                                   float* __restrict__ C) {
    extern __shared__ __align__(128) char smem[];
    const uint32_t sbase = smem_u32(smem);
    const int t = threadIdx.x;
    const int lane = t & 31, wid = t >> 5;
    const int bn = blockIdx.x * 128;
    const size_t bm = (size_t)blockIdx.y * 128;
    const int wm = (wid >> 2) * 64;
    const int wn = (wid & 3) * 32;

    const char* Ag = (const char*)g_a2 + bm * 512;
    const char* Wg = (const char*)g_wp + (size_t)bn * 512;

    auto load_chunk = [&](int c, int s) {
        uint32_t ab = sbase + s * 32768;
        uint32_t bb = ab + 16384;
        const char* Ap = Ag + c * 128;
        const char* Bp = Wg + c * 128;
#pragma unroll
        for (int i = 0; i < 4; i++) {
            int u = i * 256 + t;
            int row = u >> 3, c16 = u & 7;
            uint32_t off = (uint32_t)(row * 128 + ((c16 ^ (row & 7)) << 4));
            CP_ASYNC16(ab + off, Ap + (size_t)row * 512 + c16 * 16);
            CP_ASYNC16(bb + off, Bp + (size_t)row * 512 + c16 * 16);
        }
    };

    float acc[4][4][4];
#pragma unroll
    for (int mi = 0; mi < 4; mi++)
#pragma unroll
        for (int ni = 0; ni < 4; ni++)
#pragma unroll
            for (int q = 0; q < 4; q++) acc[mi][ni][q] = 0.0f;

    load_chunk(0, 0); CP_COMMIT();
    load_chunk(1, 1); CP_COMMIT();

    for (int c = 0; c < 4; c++) {
        if (c < 3) CP_WAIT(1); else CP_WAIT(0);
        __syncthreads();
        if (c + 2 < 4) { load_chunk(c + 2, (c + 2) % 3); CP_COMMIT(); }

        uint32_t ab = sbase + (c % 3) * 32768;
        uint32_t bb = ab + 16384;
#pragma unroll
        for (int ks = 0; ks < 4; ks++) {
            const int kc = ks * 2;
            uint32_t a_regs[4][4];
#pragma unroll
            for (int mi = 0; mi < 4; mi++) {
                int r = wm + mi * 16 + (lane & 15);
                int kk = kc + (lane >> 4);
                LDSM_X4(a_regs[mi], ab + r * 128 + ((kk ^ (r & 7)) << 4));
            }
            uint32_t b_regs[2][4];
#pragma unroll
            for (int np = 0; np < 2; np++) {
                int r = wn + np * 16 + (lane & 15);
                int kk = kc + (lane >> 4);
                LDSM_X4(b_regs[np], bb + r * 128 + ((kk ^ (r & 7)) << 4));
            }
#pragma unroll
            for (int mi = 0; mi < 4; mi++)
#pragma unroll
                for (int ni = 0; ni < 4; ni++) {
                    uint32_t b0 = b_regs[ni >> 1][ni & 1];
                    uint32_t b1 = b_regs[ni >> 1][(ni & 1) + 2];
                    MMA16816H(acc[mi][ni], a_regs[mi], b0, b1);
                }
        }
    }

    const int g = lane >> 2, tt = lane & 3;
#pragma unroll
    for (int mi = 0; mi < 4; mi++) {
        size_t r0 = bm + wm + mi * 16 + g;
#pragma unroll
        for (int ni = 0; ni < 4; ni++) {
            int col = bn + wn + ni * 8 + tt * 2;
            float bv0 = bias[col], bv1 = bias[col + 1];
            float2 v0 = make_float2(acc[mi][ni][0] + bv0, acc[mi][ni][1] + bv1);
            float2 v1 = make_float2(acc[mi][ni][2] + bv0, acc[mi][ni][3] + bv1);
            *(float2*)(C + r0 * 256 + col) = v0;
            *(float2*)(C + (r0 + 8) * 256 + col) = v1;
        }
    }
}

// ---------------- HMMA attention: held-fragment QK loop (low-LDSM) -------------
// smem: Q'[h|l|-] bf16 64x208 @0 ; K'[h|-|l] bf16 64x208 @13312 ; VtH fp16 32x144 @26624
// (dup sections unwritten/unused). sO (fp32 64x36) reuses Q' region after sync.
#define ATTN_SMEM 31232
__global__ __launch_bounds__(128, 6) void attn_mma() {
    extern __shared__ __align__(128) char smem[];
    const int b = blockIdx.x, h = blockIdx.y;
    const int t = threadIdx.x;
    const int lane = t & 31, w = t >> 5;
    const uint32_t sb = smem_u32(smem);

    const float* base = g_qkv + (size_t)b * (64 * 512) + h * 32;

    // q,k: coalesced fp32 load -> bf16 split (no duplicate-section stores)
#pragma unroll
    for (int i = 0; i < 4; i++) {
        int idx = t + i * 128;
        int n = idx >> 3;
        int d4 = (idx & 7) << 2;
        const float* rb = base + n * 512 + d4;
        float4 qv = *(const float4*)(rb);
        float4 kv = *(const float4*)(rb + 256);
        unsigned short qh[4], ql[4], kh[4], kl[4];
        split2(qv.x, qh[0], ql[0]); split2(qv.y, qh[1], ql[1]);
        split2(qv.z, qh[2], ql[2]); split2(qv.w, qh[3], ql[3]);
        split2(kv.x, kh[0], kl[0]); split2(kv.y, kh[1], kl[1]);
        split2(kv.z, kh[2], kl[2]); split2(kv.w, kh[3], kl[3]);
        uint2 qhv, qlv, khv, klv;
        qhv.x = (uint32_t)qh[0] | ((uint32_t)qh[1] << 16);
        qhv.y = (uint32_t)qh[2] | ((uint32_t)qh[3] << 16);
        qlv.x = (uint32_t)ql[0] | ((uint32_t)ql[1] << 16);
        qlv.y = (uint32_t)ql[2] | ((uint32_t)ql[3] << 16);
        khv.x = (uint32_t)kh[0] | ((uint32_t)kh[1] << 16);
        khv.y = (uint32_t)kh[2] | ((uint32_t)kh[3] << 16);
        klv.x = (uint32_t)kl[0] | ((uint32_t)kl[1] << 16);
        klv.y = (uint32_t)kl[2] | ((uint32_t)kl[3] << 16);
        char* qd = smem + n * 208 + d4 * 2;
        char* kd = smem + 13312 + n * 208 + d4 * 2;
        *(uint2*)(qd) = qhv; *(uint2*)(qd + 64) = qlv;        // q: [hi | lo]
        *(uint2*)(kd) = khv; *(uint2*)(kd + 128) = klv;       // k: [hi | -- | lo]
    }

    // V: fp16 direct load, store transposed Vt[d][m]
    {
        int m = t >> 1, dh = (t & 1) * 16;
        const __half* vr = g_v + (size_t)(b * 64 + m) * 256 + h * 32 + dh;
        unsigned short vs[16];
        *(uint4*)(vs) = *(const uint4*)(vr);
        *(uint4*)(vs + 8) = *(const uint4*)(vr + 8);
        char* vth = smem + 26624;
#pragma unroll
        for (int i = 0; i < 16; i++)
            *(unsigned short*)(vth + (dh + i) * 144 + m * 2) = vs[i];
    }
    __syncthreads();

    // ---- QK^T with held fragments: per-accumulator order = qh·kh0, qh·kh1,
    //      ql·kh0, ql·kh1, qh·kl0, qh·kl1 (bit-identical to R15's kk=0..5) ----
    const int R = w * 16;
    const uint32_t qbase = sb;
    const uint32_t kbase = sb + 13312;
    float sacc[8][4];
#pragma unroll
    for (int j = 0; j < 8; j++)
#pragma unroll
        for (int q = 0; q < 4; q++) sacc[j][q] = 0.0f;

    uint32_t aq0[4], aq1[4], al0[4], al1[4];
    {
        int r = R + (lane & 15);
        int c = lane >> 4;
        LDSM_X4(aq0, qbase + r * 208 + (0 + c) * 16);
        LDSM_X4(aq1, qbase + r * 208 + (2 + c) * 16);
        LDSM_X4(al0, qbase + r * 208 + (4 + c) * 16);
        LDSM_X4(al1, qbase + r * 208 + (6 + c) * 16);
    }
#pragma unroll
    for (int np = 0; np < 2; np++) {
        const int c = lane >> 4;
        uint32_t bk[2][2][4];
#pragma unroll
        for (int j = 0; j < 2; j++) {
            int r = (np * 2 + j) * 16 + (lane & 15);
            LDSM_X4(bk[j][0], kbase + r * 208 + (0 + c) * 16);   // kh step0
            LDSM_X4(bk[j][1], kbase + r * 208 + (2 + c) * 16);   // kh step1
        }
#pragma unroll
        for (int j = 0; j < 2; j++) {
            int nt = np * 2 + j;
            MMA16816(sacc[nt * 2 + 0], aq0, bk[j][0][0], bk[j][0][2]);
            MMA16816(sacc[nt * 2 + 1], aq0, bk[j][0][1], bk[j][0][3]);
            MMA16816(sacc[nt * 2 + 0], aq1, bk[j][1][0], bk[j][1][2]);
            MMA16816(sacc[nt * 2 + 1], aq1, bk[j][1][1], bk[j][1][3]);
            MMA16816(sacc[nt * 2 + 0], al0, bk[j][0][0], bk[j][0][2]);
            MMA16816(sacc[nt * 2 + 1], al0, bk[j][0][1], bk[j][0][3]);
            MMA16816(sacc[nt * 2 + 0], al1, bk[j][1][0], bk[j][1][2]);
            MMA16816(sacc[nt * 2 + 1], al1, bk[j][1][1], bk[j][1][3]);
        }
#pragma unroll
        for (int j = 0; j < 2; j++) {
            int r = (np * 2 + j) * 16 + (lane & 15);
            LDSM_X4(bk[j][0], kbase + r * 208 + (8 + c) * 16);   // kl step0
            LDSM_X4(bk[j][1], kbase + r * 208 + (10 + c) * 16);  // kl step1
        }
#pragma unroll
        for (int j = 0; j < 2; j++) {
            int nt = np * 2 + j;
            MMA16816(sacc[nt * 2 + 0], aq0, bk[j][0][0], bk[j][0][2]);
            MMA16816(sacc[nt * 2 + 1], aq0, bk[j][0][1], bk[j][0][3]);
            MMA16816(sacc[nt * 2 + 0], aq1, bk[j][1][0], bk[j][1][2]);
            MMA16816(sacc[nt * 2 + 1], aq1, bk[j][1][1], bk[j][1][3]);
        }
    }

    // ---- bias (fragment-permuted float4 loads) + softmax ----
    const int g = lane >> 2, tt = lane & 3;
    const float* bp0 = g_bias16 + (((h * 64 + R + g) << 6) + tt * 16);
    const float* bp1 = bp0 + (8 << 6);
    float4 b0v[4], b1v[4];
#pragma unroll
    for (int q = 0; q < 4; q++) {
        b0v[q] = *(const float4*)(bp0 + q * 4);
        b1v[q] = *(const float4*)(bp1 + q * 4);
    }
#pragma unroll
    for (int j = 0; j < 8; j++) {
        float4 c0 = b0v[j >> 1], c1 = b1v[j >> 1];
        float e0 = (j & 1) ? c0.z : c0.x;
        float e1 = (j & 1) ? c0.w : c0.y;
        float e2 = (j & 1) ? c1.z : c1.x;
        float e3 = (j & 1) ? c1.w : c1.y;
        sacc[j][0] += e0; sacc[j][1] += e1;
        sacc[j][2] += e2; sacc[j][3] += e3;
    }
    float m0 = -1e30f, m1 = -1e30f;
#pragma unroll
    for (int j = 0; j < 8; j++) {
        m0 = fmaxf(m0, fmaxf(sacc[j][0], sacc[j][1]));
        m1 = fmaxf(m1, fmaxf(sacc[j][2], sacc[j][3]));
    }
    m0 = fmaxf(m0, __shfl_xor_sync(0xffffffffu, m0, 1));
    m0 = fmaxf(m0, __shfl_xor_sync(0xffffffffu, m0, 2));
    m1 = fmaxf(m1, __shfl_xor_sync(0xffffffffu, m1, 1));
    m1 = fmaxf(m1, __shfl_xor_sync(0xffffffffu, m1, 2));
    float s0 = 0.0f, s1 = 0.0f;
#pragma unroll
    for (int j = 0; j < 8; j++) {
        sacc[j][0] = __expf(sacc[j][0] - m0);
        sacc[j][1] = __expf(sacc[j][1] - m0);
        sacc[j][2] = __expf(sacc[j][2] - m1);
        sacc[j][3] = __expf(sacc[j][3] - m1);
        s0 += sacc[j][0] + sacc[j][1];
        s1 += sacc[j][2] + sacc[j][3];
    }
    s0 += __shfl_xor_sync(0xffffffffu, s0, 1);
    s0 += __shfl_xor_sync(0xffffffffu, s0, 2);
    s1 += __shfl_xor_sync(0xffffffffu, s1, 1);
    s1 += __shfl_xor_sync(0xffffffffu, s1, 2);
    float r0 = 1.0f / s0, r1 = 1.0f / s1;

    // ---- P fp16-hi B-fragments from registers ----
    uint32_t bh[8][2];
#pragma unroll
    for (int j = 0; j < 8; j++) {
        float p0 = sacc[j][0] * r0, p1 = sacc[j][1] * r0;
        float p2 = sacc[j][2] * r1, p3 = sacc[j][3] * r1;
        bh[j][0] = (uint32_t)h_of(p0) | ((uint32_t)h_of(p1) << 16);
        bh[j][1] = (uint32_t)h_of(p2) | ((uint32_t)h_of(p3) << 16);
    }

    // ---- O^T = V^T P^T: single fp16 pass ----
    float oacc[2][2][4];
#pragma unroll
    for (int mt = 0; mt < 2; mt++)
#pragma unroll
        for (int nt = 0; nt < 2; nt++)
#pragma unroll
            for (int q = 0; q < 4; q++) oacc[mt][nt][q] = 0.0f;

    {
        const uint32_t vbase = sb + 26624;
#pragma unroll
        for (int mt = 0; mt < 2; mt++) {
#pragma unroll
            for (int s = 0; s < 4; s++) {
                uint32_t a[4];
                int r = mt * 16 + (lane & 15);
                int ch = 2 * s + (lane >> 4);
                LDSM_X4(a, vbase + r * 144 + ch * 16);
                MMA16816H(oacc[mt][0], a, bh[2 * s][0], bh[2 * s + 1][0]);
                MMA16816H(oacc[mt][1], a, bh[2 * s][1], bh[2 * s + 1][1]);
            }
        }
    }

    // ---- stage O (transpose back), coalesced fp16-hi write ----
    __syncthreads();
    float* sO = (float*)smem;
#pragma unroll
    for (int mt = 0; mt < 2; mt++)
#pragma unroll
        for (int nt = 0; nt < 2; nt++) {
            int qr = R + nt * 8 + tt * 2;
            int d = mt * 16 + g;
            sO[qr * 36 + d] = oacc[mt][nt][0];
            sO[(qr + 1) * 36 + d] = oacc[mt][nt][1];
            sO[qr * 36 + d + 8] = oacc[mt][nt][2];
            sO[(qr + 1) * 36 + d + 8] = oacc[mt][nt][3];
        }
    __syncthreads();

    {
        int qr = t >> 1, dh = (t & 1) * 16;
        const float* orow = sO + qr * 36 + dh;
        unsigned short hi[16];
#pragma unroll
        for (int i = 0; i < 16; i++) hi[i] = h_of(orow[i]);
        __half* og = g_a2 + (size_t)(b * 64 + qr) * 256 + h * 32 + dh;
        uint4 hv0, hv1;
        hv0.x = (uint32_t)hi[0] | ((uint32_t)hi[1] << 16);
        hv0.y = (uint32_t)hi[2] | ((uint32_t)hi[3] << 16);
        hv0.z = (uint32_t)hi[4] | ((uint32_t)hi[5] << 16);
        hv0.w = (uint32_t)hi[6] | ((uint32_t)hi[7] << 16);
        hv1.x = (uint32_t)hi[8] | ((uint32_t)hi[9] << 16);
        hv1.y = (uint32_t)hi[10] | ((uint32_t)hi[11] << 16);
        hv1.z = (uint32_t)hi[12] | ((uint32_t)hi[13] << 16);
        hv1.w = (uint32_t)hi[14] | ((uint32_t)hi[15] << 16);
        *(uint4*)(og) = hv0;
        *(uint4*)(og + 8) = hv1;
    }
}

extern "C" void kernel_launch(void* const* d_in, const int* in_sizes, int n_in,
                              void* d_out, int out_size) {
    const float* x           = (const float*)d_in[0];
    const float* qkv_w       = (const float*)d_in[1];
    const float* q_bias      = (const float*)d_in[2];
    const float* v_bias      = (const float*)d_in[3];
    const float* logit_scale = (const float*)d_in[4];
    const float* cpb_w1      = (const float*)d_in[5];
    const float* cpb_b1      = (const float*)d_in[6];
    const float* cpb_w2      = (const float*)d_in[7];
    const float* proj_w      = (const float*)d_in[8];
    const float* proj_b      = (const float*)d_in[9];
    float* out = (float*)d_out;

    const int GEMM_SMEM = 3 * 32768;  // 96 KB, 2 CTAs/SM
    cudaFuncSetAttribute(qkv_mma, cudaFuncAttributeMaxDynamicSharedMemorySize, GEMM_SMEM);
    cudaFuncSetAttribute(proj_mma, cudaFuncAttributeMaxDynamicSharedMemorySize, GEMM_SMEM);
    cudaFuncSetAttribute(attn_mma, cudaFuncAttributeMaxDynamicSharedMemorySize, ATTN_SMEM);

    prep_all<<<1 + ACT_BLOCKS + WQ_BLOCKS + WP_BLOCKS, 256>>>(
        x, qkv_w, proj_w, cpb_w1, cpb_b1, cpb_w2, q_bias, v_bias);
    qkv_mma<<<dim3(6, M_TOTAL / 128), 256, GEMM_SMEM>>>(logit_scale);
    attn_mma<<<dim3(2048, 8), 128, ATTN_SMEM>>>();
    proj_mma<<<dim3(2, M_TOTAL / 128), 256, GEMM_SMEM>>>(proj_b, out);
}